// round 1
// baseline (speedup 1.0000x reference)
#include <cuda_runtime.h>
#include <cuda_bf16.h>
#include <math.h>

// Problem constants
#define NB   4
#define SEQ  2048
#define DIM  1024
#define HEADS 16
#define HD   64
#define NS   (NB*SEQ)          // 8192
#define NH   (NB*HEADS)        // 64
#define NEGC 1000000000.0f

// Scratch (device globals; allocation at module load, allowed)
__device__ float g_q[(size_t)NH * SEQ * HD];     // [nh][s][d]
__device__ float g_k[(size_t)NH * SEQ * HD];
__device__ float g_v[(size_t)NH * SEQ * HD];
__device__ float g_pv[(size_t)NH * SEQ * HD];    // exclusive prefix sum of v over s
__device__ float g_attn[(size_t)NS * DIM];       // [n*s][h*d] attention block output

// ---------------------------------------------------------------------------
// Kernel 1: fused QKV projection.  C = X @ W^T  (NT gemm)
// X: [8192,1024] row-major, W: [1024,1024] row-major (C[i,j]=sum_k X[i,k]W[j,k])
// grid: (16, 128, 3)  block: 256.  BM=BN=64, BK=16, 4x4 micro-tile per thread.
// Writes directly into head layout g_{q,k,v}[((n*16+h)*2048+s)*64+dd].
// ---------------------------------------------------------------------------
__global__ void __launch_bounds__(256) gemm_qkv_kernel(
    const float* __restrict__ x,
    const float* __restrict__ wq,
    const float* __restrict__ wk,
    const float* __restrict__ wv)
{
    __shared__ float As[16][65];
    __shared__ float Bs[16][65];

    const float* w   = (blockIdx.z == 0) ? wq : (blockIdx.z == 1 ? wk : wv);
    float*       dst = (blockIdx.z == 0) ? g_q : (blockIdx.z == 1 ? g_k : g_v);

    const int tid = threadIdx.x;
    const int ty  = tid >> 4;       // 0..15
    const int tx  = tid & 15;       // 0..15
    const int lr  = tid >> 2;       // 0..63 (load row)
    const int lv  = tid & 3;        // 0..3  (load vec)

    const int row0 = blockIdx.y * 64;
    const int col0 = blockIdx.x * 64;

    float acc[4][4] = {};

    for (int k0 = 0; k0 < DIM; k0 += 16) {
        float4 a4 = *(const float4*)(x + (size_t)(row0 + lr) * DIM + k0 + lv * 4);
        float4 b4 = *(const float4*)(w + (size_t)(col0 + lr) * DIM + k0 + lv * 4);
        As[lv*4+0][lr] = a4.x; As[lv*4+1][lr] = a4.y;
        As[lv*4+2][lr] = a4.z; As[lv*4+3][lr] = a4.w;
        Bs[lv*4+0][lr] = b4.x; Bs[lv*4+1][lr] = b4.y;
        Bs[lv*4+2][lr] = b4.z; Bs[lv*4+3][lr] = b4.w;
        __syncthreads();

        #pragma unroll
        for (int kk = 0; kk < 16; kk++) {
            float a[4], b[4];
            #pragma unroll
            for (int i = 0; i < 4; i++) a[i] = As[kk][ty*4 + i];
            #pragma unroll
            for (int j = 0; j < 4; j++) b[j] = Bs[kk][tx*4 + j];
            #pragma unroll
            for (int i = 0; i < 4; i++)
                #pragma unroll
                for (int j = 0; j < 4; j++)
                    acc[i][j] = fmaf(a[i], b[j], acc[i][j]);
        }
        __syncthreads();
    }

    // epilogue: write to [nh][s][dd] layout
    const int hh = blockIdx.x;          // col0/64 : whole 64-col block is one head
    #pragma unroll
    for (int i = 0; i < 4; i++) {
        int r = row0 + ty*4 + i;
        int n = r >> 11;
        int s = r & (SEQ - 1);
        float4 v4;
        v4.x = acc[i][0]; v4.y = acc[i][1]; v4.z = acc[i][2]; v4.w = acc[i][3];
        float* p = dst + ((((size_t)n * HEADS + hh) * SEQ + s) * HD) + tx*4;
        *(float4*)p = v4;
    }
}

// ---------------------------------------------------------------------------
// Kernel 2: exclusive prefix sum of v along s, per (nh, dd) column.
// grid: 64 blocks (nh), 64 threads (dd).
// ---------------------------------------------------------------------------
__global__ void prefix_kernel()
{
    const int nh = blockIdx.x;
    const int dd = threadIdx.x;
    const float* v  = g_v  + (size_t)nh * SEQ * HD + dd;
    float*       pv = g_pv + (size_t)nh * SEQ * HD + dd;
    float run = 0.0f;
    for (int t = 0; t < SEQ; t++) {
        pv[(size_t)t * HD] = run;
        run += v[(size_t)t * HD];
    }
}

// ---------------------------------------------------------------------------
// Kernel 3: flash attention (NO causal mask inside softmax) + post-softmax
// mask correction:   out = softmax(QK^T * scale) @ V  -  1e9 * prefixsum(V)
// BM=BN=64, d=64, fp32. grid: (32, 64) block: 256. dynamic smem ~65.8KB.
// ---------------------------------------------------------------------------
#define ATTN_SMEM ((3 * 64 * 64 + 64 * 65) * 4)

__global__ void __launch_bounds__(256) attn_kernel()
{
    extern __shared__ float sm[];
    float* Qs = sm;               // [dd][r]   4096
    float* Ks = sm + 4096;        // [dd][c]   4096
    float* Vs = sm + 8192;        // [t][dd]   4096
    float* Ps = sm + 12288;       // [t][r]    64*65

    const int nh = blockIdx.y;
    const int q0 = blockIdx.x * 64;
    const float* qg = g_q + (size_t)nh * SEQ * HD;
    const float* kg = g_k + (size_t)nh * SEQ * HD;
    const float* vg = g_v + (size_t)nh * SEQ * HD;

    const int tid = threadIdx.x;
    const int ty = tid >> 4, tx = tid & 15;
    const int lr = tid >> 2, lv = tid & 3;
    const float attn_scale = 0.125f;   // 1/sqrt(64)

    // load Q (scaled), transposed to [dd][r]
    #pragma unroll
    for (int rep = 0; rep < 4; rep++) {
        float4 t4 = *(const float4*)(qg + (size_t)(q0 + lr) * HD + rep*16 + lv*4);
        int dd = rep*16 + lv*4;
        Qs[(dd+0)*64 + lr] = t4.x * attn_scale;
        Qs[(dd+1)*64 + lr] = t4.y * attn_scale;
        Qs[(dd+2)*64 + lr] = t4.z * attn_scale;
        Qs[(dd+3)*64 + lr] = t4.w * attn_scale;
    }

    float o[4][4] = {};
    float m[4], l[4];
    #pragma unroll
    for (int i = 0; i < 4; i++) { m[i] = -1e30f; l[i] = 0.0f; }

    for (int kt = 0; kt < SEQ / 64; kt++) {
        // load K transposed [dd][c], V natural [t][dd]
        #pragma unroll
        for (int rep = 0; rep < 4; rep++) {
            float4 k4 = *(const float4*)(kg + (size_t)(kt*64 + lr) * HD + rep*16 + lv*4);
            int dd = rep*16 + lv*4;
            Ks[(dd+0)*64 + lr] = k4.x;
            Ks[(dd+1)*64 + lr] = k4.y;
            Ks[(dd+2)*64 + lr] = k4.z;
            Ks[(dd+3)*64 + lr] = k4.w;
            float4 v4 = *(const float4*)(vg + (size_t)(kt*64 + lr) * HD + rep*16 + lv*4);
            *(float4*)(Vs + lr*64 + rep*16 + lv*4) = v4;
        }
        __syncthreads();

        // scores: s_[i][j] = sum_dd Q[dd][ty4+i] * K[dd][tx4+j]
        float s_[4][4] = {};
        #pragma unroll 4
        for (int dd = 0; dd < 64; dd++) {
            float4 a4 = *(const float4*)(Qs + dd*64 + ty*4);
            float4 b4 = *(const float4*)(Ks + dd*64 + tx*4);
            s_[0][0] = fmaf(a4.x, b4.x, s_[0][0]); s_[0][1] = fmaf(a4.x, b4.y, s_[0][1]);
            s_[0][2] = fmaf(a4.x, b4.z, s_[0][2]); s_[0][3] = fmaf(a4.x, b4.w, s_[0][3]);
            s_[1][0] = fmaf(a4.y, b4.x, s_[1][0]); s_[1][1] = fmaf(a4.y, b4.y, s_[1][1]);
            s_[1][2] = fmaf(a4.y, b4.z, s_[1][2]); s_[1][3] = fmaf(a4.y, b4.w, s_[1][3]);
            s_[2][0] = fmaf(a4.z, b4.x, s_[2][0]); s_[2][1] = fmaf(a4.z, b4.y, s_[2][1]);
            s_[2][2] = fmaf(a4.z, b4.z, s_[2][2]); s_[2][3] = fmaf(a4.z, b4.w, s_[2][3]);
            s_[3][0] = fmaf(a4.w, b4.x, s_[3][0]); s_[3][1] = fmaf(a4.w, b4.y, s_[3][1]);
            s_[3][2] = fmaf(a4.w, b4.z, s_[3][2]); s_[3][3] = fmaf(a4.w, b4.w, s_[3][3]);
        }

        // online softmax (row reduce across the 16 threads of each row group)
        #pragma unroll
        for (int i = 0; i < 4; i++) {
            float rmax = fmaxf(fmaxf(s_[i][0], s_[i][1]), fmaxf(s_[i][2], s_[i][3]));
            #pragma unroll
            for (int off = 8; off >= 1; off >>= 1)
                rmax = fmaxf(rmax, __shfl_xor_sync(0xffffffffu, rmax, off));
            float mn   = fmaxf(m[i], rmax);
            float corr = __expf(m[i] - mn);
            float p0 = __expf(s_[i][0] - mn);
            float p1 = __expf(s_[i][1] - mn);
            float p2 = __expf(s_[i][2] - mn);
            float p3 = __expf(s_[i][3] - mn);
            float rs = (p0 + p1) + (p2 + p3);
            #pragma unroll
            for (int off = 8; off >= 1; off >>= 1)
                rs += __shfl_xor_sync(0xffffffffu, rs, off);
            l[i] = l[i] * corr + rs;
            m[i] = mn;
            o[i][0] *= corr; o[i][1] *= corr; o[i][2] *= corr; o[i][3] *= corr;
            Ps[(tx*4+0)*65 + ty*4 + i] = p0;
            Ps[(tx*4+1)*65 + ty*4 + i] = p1;
            Ps[(tx*4+2)*65 + ty*4 + i] = p2;
            Ps[(tx*4+3)*65 + ty*4 + i] = p3;
        }
        __syncthreads();

        // O += P @ V
        #pragma unroll 4
        for (int t = 0; t < 64; t++) {
            float4 v4 = *(const float4*)(Vs + t*64 + tx*4);
            float pa = Ps[t*65 + ty*4 + 0];
            float pb = Ps[t*65 + ty*4 + 1];
            float pc = Ps[t*65 + ty*4 + 2];
            float pd = Ps[t*65 + ty*4 + 3];
            o[0][0] = fmaf(pa, v4.x, o[0][0]); o[0][1] = fmaf(pa, v4.y, o[0][1]);
            o[0][2] = fmaf(pa, v4.z, o[0][2]); o[0][3] = fmaf(pa, v4.w, o[0][3]);
            o[1][0] = fmaf(pb, v4.x, o[1][0]); o[1][1] = fmaf(pb, v4.y, o[1][1]);
            o[1][2] = fmaf(pb, v4.z, o[1][2]); o[1][3] = fmaf(pb, v4.w, o[1][3]);
            o[2][0] = fmaf(pc, v4.x, o[2][0]); o[2][1] = fmaf(pc, v4.y, o[2][1]);
            o[2][2] = fmaf(pc, v4.z, o[2][2]); o[2][3] = fmaf(pc, v4.w, o[2][3]);
            o[3][0] = fmaf(pd, v4.x, o[3][0]); o[3][1] = fmaf(pd, v4.y, o[3][1]);
            o[3][2] = fmaf(pd, v4.z, o[3][2]); o[3][3] = fmaf(pd, v4.w, o[3][3]);
        }
        __syncthreads();
    }

    // epilogue: out = o / l  - 1e9 * pv ; write into [n*s][h*64+dd]
    const int n  = nh >> 4;
    const int hh = nh & 15;
    #pragma unroll
    for (int i = 0; i < 4; i++) {
        int s = q0 + ty*4 + i;
        float inv = 1.0f / l[i];
        const float* pvp = g_pv + ((size_t)nh * SEQ + s) * HD + tx*4;
        float4 pv4 = *(const float4*)pvp;
        float4 r;
        r.x = o[i][0] * inv - NEGC * pv4.x;
        r.y = o[i][1] * inv - NEGC * pv4.y;
        r.z = o[i][2] * inv - NEGC * pv4.z;
        r.w = o[i][3] * inv - NEGC * pv4.w;
        float* dst = g_attn + ((size_t)(n * SEQ + s)) * DIM + hh * HD + tx*4;
        *(float4*)dst = r;
    }
}

// ---------------------------------------------------------------------------
// Kernel 4: output projection  out = g_attn @ wo^T + bo
// grid: (16, 128)  block 256.  Same NT tiling as kernel 1.
// ---------------------------------------------------------------------------
__global__ void __launch_bounds__(256) gemm_out_kernel(
    const float* __restrict__ wo,
    const float* __restrict__ bo,
    float* __restrict__ out)
{
    __shared__ float As[16][65];
    __shared__ float Bs[16][65];

    const int tid = threadIdx.x;
    const int ty = tid >> 4, tx = tid & 15;
    const int lr = tid >> 2, lv = tid & 3;
    const int row0 = blockIdx.y * 64;
    const int col0 = blockIdx.x * 64;

    float acc[4][4] = {};

    for (int k0 = 0; k0 < DIM; k0 += 16) {
        float4 a4 = *(const float4*)(g_attn + (size_t)(row0 + lr) * DIM + k0 + lv * 4);
        float4 b4 = *(const float4*)(wo     + (size_t)(col0 + lr) * DIM + k0 + lv * 4);
        As[lv*4+0][lr] = a4.x; As[lv*4+1][lr] = a4.y;
        As[lv*4+2][lr] = a4.z; As[lv*4+3][lr] = a4.w;
        Bs[lv*4+0][lr] = b4.x; Bs[lv*4+1][lr] = b4.y;
        Bs[lv*4+2][lr] = b4.z; Bs[lv*4+3][lr] = b4.w;
        __syncthreads();

        #pragma unroll
        for (int kk = 0; kk < 16; kk++) {
            float a[4], b[4];
            #pragma unroll
            for (int i = 0; i < 4; i++) a[i] = As[kk][ty*4 + i];
            #pragma unroll
            for (int j = 0; j < 4; j++) b[j] = Bs[kk][tx*4 + j];
            #pragma unroll
            for (int i = 0; i < 4; i++)
                #pragma unroll
                for (int j = 0; j < 4; j++)
                    acc[i][j] = fmaf(a[i], b[j], acc[i][j]);
        }
        __syncthreads();
    }

    const int c0 = col0 + tx*4;
    float4 bia = *(const float4*)(bo + c0);
    #pragma unroll
    for (int i = 0; i < 4; i++) {
        int r = row0 + ty*4 + i;
        float4 v4;
        v4.x = acc[i][0] + bia.x;
        v4.y = acc[i][1] + bia.y;
        v4.z = acc[i][2] + bia.z;
        v4.w = acc[i][3] + bia.w;
        *(float4*)(out + (size_t)r * DIM + c0) = v4;
    }
}

// ---------------------------------------------------------------------------
extern "C" void kernel_launch(void* const* d_in, const int* in_sizes, int n_in,
                              void* d_out, int out_size)
{
    const float* x  = (const float*)d_in[0];
    const float* wq = (const float*)d_in[1];
    const float* wk = (const float*)d_in[2];
    const float* wv = (const float*)d_in[3];
    const float* wo = (const float*)d_in[4];
    const float* bo = (const float*)d_in[5];
    float* out = (float*)d_out;

    cudaFuncSetAttribute(attn_kernel,
                         cudaFuncAttributeMaxDynamicSharedMemorySize, ATTN_SMEM);

    gemm_qkv_kernel<<<dim3(DIM/64, NS/64, 3), 256>>>(x, wq, wk, wv);
    prefix_kernel<<<NH, HD>>>();
    attn_kernel<<<dim3(SEQ/64, NH), 256, ATTN_SMEM>>>();
    gemm_out_kernel<<<dim3(DIM/64, NS/64), 256>>>(wo, bo, out);
}

// round 2
// speedup vs baseline: 1.3523x; 1.3523x over previous
#include <cuda_runtime.h>
#include <cuda_bf16.h>
#include <math.h>

// Problem constants
#define NB    4
#define SEQ   2048
#define DIM   1024
#define HEADS 16
#define HD    64
#define NS    (NB*SEQ)          // 8192
#define NH    (NB*HEADS)        // 64
#define NEGC  1000000000.0f

// Scratch
__device__ float g_q[(size_t)NH * SEQ * HD];
__device__ float g_k[(size_t)NH * SEQ * HD];
__device__ float g_v[(size_t)NH * SEQ * HD];
__device__ float g_pv[(size_t)NH * SEQ * HD];
__device__ float g_attn[(size_t)NS * DIM];

// ---------------------------------------------------------------------------
// SGEMM core: C = A @ B^T, 128x128 tile, BK=8, 256 threads, 8x8 microtile.
// As/Bs stored k-major with stride 132 (conflict-free STS + aligned LDS.128).
// ---------------------------------------------------------------------------
#define TSTR 132

__device__ __forceinline__ void sgemm_core(
    const float* __restrict__ A, const float* __restrict__ B,
    int row0, int col0, float* As, float* Bs, float acc[8][8])
{
    const int tid = threadIdx.x;
    const int tx = tid & 15, ty = tid >> 4;
    const int lr = tid >> 1;          // 0..127
    const int lc = (tid & 1) * 4;     // 0 or 4

    const float* aP = A + (size_t)(row0 + lr) * DIM + lc;
    const float* bP = B + (size_t)(col0 + lr) * DIM + lc;
    float4 aReg = *(const float4*)aP;
    float4 bReg = *(const float4*)bP;

    for (int k0 = 0; k0 < DIM; k0 += 8) {
        As[(lc+0)*TSTR + lr] = aReg.x;
        As[(lc+1)*TSTR + lr] = aReg.y;
        As[(lc+2)*TSTR + lr] = aReg.z;
        As[(lc+3)*TSTR + lr] = aReg.w;
        Bs[(lc+0)*TSTR + lr] = bReg.x;
        Bs[(lc+1)*TSTR + lr] = bReg.y;
        Bs[(lc+2)*TSTR + lr] = bReg.z;
        Bs[(lc+3)*TSTR + lr] = bReg.w;
        __syncthreads();

        if (k0 + 8 < DIM) {
            aReg = *(const float4*)(aP + k0 + 8);
            bReg = *(const float4*)(bP + k0 + 8);
        }

        #pragma unroll
        for (int kk = 0; kk < 8; kk++) {
            float4 a0 = *(const float4*)&As[kk*TSTR + ty*8];
            float4 a1 = *(const float4*)&As[kk*TSTR + ty*8 + 4];
            float4 b0 = *(const float4*)&Bs[kk*TSTR + tx*8];
            float4 b1 = *(const float4*)&Bs[kk*TSTR + tx*8 + 4];
            float av[8] = {a0.x,a0.y,a0.z,a0.w,a1.x,a1.y,a1.z,a1.w};
            float bv[8] = {b0.x,b0.y,b0.z,b0.w,b1.x,b1.y,b1.z,b1.w};
            #pragma unroll
            for (int i = 0; i < 8; i++)
                #pragma unroll
                for (int j = 0; j < 8; j++)
                    acc[i][j] = fmaf(av[i], bv[j], acc[i][j]);
        }
        __syncthreads();
    }
}

// ---------------------------------------------------------------------------
// Kernel 1: fused QKV projection, epilogue scatters into [nh][s][dd] layout.
// grid (8, 64, 3), block 256
// ---------------------------------------------------------------------------
__global__ void __launch_bounds__(256) gemm_qkv_kernel(
    const float* __restrict__ x,
    const float* __restrict__ wq,
    const float* __restrict__ wk,
    const float* __restrict__ wv)
{
    __shared__ float As[8*TSTR];
    __shared__ float Bs[8*TSTR];

    const float* w   = (blockIdx.z == 0) ? wq : (blockIdx.z == 1 ? wk : wv);
    float*       dst = (blockIdx.z == 0) ? g_q : (blockIdx.z == 1 ? g_k : g_v);

    const int row0 = blockIdx.y * 128;
    const int col0 = blockIdx.x * 128;
    float acc[8][8] = {};

    sgemm_core(x, w, row0, col0, As, Bs, acc);

    const int tx = threadIdx.x & 15, ty = threadIdx.x >> 4;
    const int cb  = col0 + tx * 8;
    const int hh  = cb >> 6;
    const int dd0 = cb & 63;
    #pragma unroll
    for (int i = 0; i < 8; i++) {
        int r = row0 + ty*8 + i;
        int n = r >> 11;
        int s = r & (SEQ - 1);
        float* p = dst + (((size_t)(n * HEADS + hh) * SEQ + s) * HD) + dd0;
        float4 v0 = {acc[i][0], acc[i][1], acc[i][2], acc[i][3]};
        float4 v1 = {acc[i][4], acc[i][5], acc[i][6], acc[i][7]};
        *(float4*)(p)     = v0;
        *(float4*)(p + 4) = v1;
    }
}

// ---------------------------------------------------------------------------
// Kernel 2: exclusive prefix sum of v along s (per nh, dd column)
// ---------------------------------------------------------------------------
__global__ void prefix_kernel()
{
    const int nh = blockIdx.x;
    const int dd = threadIdx.x;
    const float* v  = g_v  + (size_t)nh * SEQ * HD + dd;
    float*       pv = g_pv + (size_t)nh * SEQ * HD + dd;
    float run = 0.0f;
    for (int t = 0; t < SEQ; t++) {
        pv[(size_t)t * HD] = run;
        run += v[(size_t)t * HD];
    }
}

// ---------------------------------------------------------------------------
// Kernel 3: flash attention (no mask in softmax) + post-softmax correction
//   out = softmax(QK^T/8) @ V  -  1e9 * prefixsum(V)
// BM=128, BN=64, 256 threads, 8x4 microtile. grid (16, 64).
// ---------------------------------------------------------------------------
#define QS 132
#define KS 66
#define VS 68
#define PS 68
#define ATTN_SMEM ((64*QS + 64*KS + 64*VS + 128*PS) * 4)

__global__ void __launch_bounds__(256) attn_kernel()
{
    extern __shared__ float sm[];
    float* Qs = sm;                   // [dd][r]  transposed, stride 132
    float* Ks = Qs + 64*QS;           // [dd][c]  transposed, stride 66
    float* Vs = Ks + 64*KS;           // [t][dd]  natural,    stride 68
    float* Ps = Vs + 64*VS;           // [r][t]   natural,    stride 68

    const int tid = threadIdx.x;
    const int tx = tid & 15, ty = tid >> 4;
    const int nh = blockIdx.y;
    const int q0 = blockIdx.x * 128;
    const float* qg = g_q + (size_t)nh * SEQ * HD;
    const float* kg = g_k + (size_t)nh * SEQ * HD;
    const float* vg = g_v + (size_t)nh * SEQ * HD;

    // load Q (scaled by 1/8), transposed. 8192 floats = 4096 float2, 16 reps.
    #pragma unroll
    for (int rep = 0; rep < 16; rep++) {
        int idx2 = rep*256 + tid;
        int r  = idx2 >> 5;
        int dd = (idx2 & 31) * 2;
        float2 t2 = *(const float2*)(qg + (size_t)(q0 + r) * HD + dd);
        Qs[dd*QS + r]     = t2.x * 0.125f;
        Qs[(dd+1)*QS + r] = t2.y * 0.125f;
    }

    float o[8][4] = {};
    float m[8], l[8];
    #pragma unroll
    for (int i = 0; i < 8; i++) { m[i] = -1e30f; l[i] = 0.0f; }

    for (int kt = 0; kt < SEQ/64; kt++) {
        // K tile transposed (float2 path), V tile natural (float4 path)
        #pragma unroll
        for (int rep = 0; rep < 8; rep++) {
            int idx2 = rep*256 + tid;
            int t  = idx2 >> 5;
            int dd = (idx2 & 31) * 2;
            float2 k2 = *(const float2*)(kg + (size_t)(kt*64 + t) * HD + dd);
            Ks[dd*KS + t]     = k2.x;
            Ks[(dd+1)*KS + t] = k2.y;
        }
        #pragma unroll
        for (int rep = 0; rep < 4; rep++) {
            int idx4 = rep*256 + tid;
            int t = idx4 >> 4;
            int c = (idx4 & 15) * 4;
            *(float4*)&Vs[t*VS + c] = *(const float4*)(vg + (size_t)(kt*64 + t) * HD + c);
        }
        __syncthreads();

        // scores s_[i][j] = sum_dd Q[dd][ty8+i] * K[dd][tx4+j]
        float s_[8][4] = {};
        #pragma unroll 8
        for (int dd = 0; dd < 64; dd++) {
            float4 a0 = *(const float4*)&Qs[dd*QS + ty*8];
            float4 a1 = *(const float4*)&Qs[dd*QS + ty*8 + 4];
            float2 b0 = *(const float2*)&Ks[dd*KS + tx*4];
            float2 b1 = *(const float2*)&Ks[dd*KS + tx*4 + 2];
            float av[8] = {a0.x,a0.y,a0.z,a0.w,a1.x,a1.y,a1.z,a1.w};
            #pragma unroll
            for (int i = 0; i < 8; i++) {
                s_[i][0] = fmaf(av[i], b0.x, s_[i][0]);
                s_[i][1] = fmaf(av[i], b0.y, s_[i][1]);
                s_[i][2] = fmaf(av[i], b1.x, s_[i][2]);
                s_[i][3] = fmaf(av[i], b1.y, s_[i][3]);
            }
        }

        // online softmax (reduce across 16 tx lanes; lane = (ty&1)<<4 | tx)
        #pragma unroll
        for (int i = 0; i < 8; i++) {
            float rmax = fmaxf(fmaxf(s_[i][0], s_[i][1]), fmaxf(s_[i][2], s_[i][3]));
            #pragma unroll
            for (int off = 8; off >= 1; off >>= 1)
                rmax = fmaxf(rmax, __shfl_xor_sync(0xffffffffu, rmax, off));
            float mn   = fmaxf(m[i], rmax);
            float corr = __expf(m[i] - mn);
            float p0 = __expf(s_[i][0] - mn);
            float p1 = __expf(s_[i][1] - mn);
            float p2 = __expf(s_[i][2] - mn);
            float p3 = __expf(s_[i][3] - mn);
            float rs = (p0 + p1) + (p2 + p3);
            #pragma unroll
            for (int off = 8; off >= 1; off >>= 1)
                rs += __shfl_xor_sync(0xffffffffu, rs, off);
            l[i] = l[i] * corr + rs;
            m[i] = mn;
            o[i][0] *= corr; o[i][1] *= corr; o[i][2] *= corr; o[i][3] *= corr;
            float4 p4 = {p0, p1, p2, p3};
            *(float4*)&Ps[(ty*8 + i)*PS + tx*4] = p4;
        }
        __syncthreads();

        // O += P @ V, 4 t's at a time
        #pragma unroll 4
        for (int tt = 0; tt < 16; tt++) {
            float4 v0 = *(const float4*)&Vs[(4*tt+0)*VS + tx*4];
            float4 v1 = *(const float4*)&Vs[(4*tt+1)*VS + tx*4];
            float4 v2 = *(const float4*)&Vs[(4*tt+2)*VS + tx*4];
            float4 v3 = *(const float4*)&Vs[(4*tt+3)*VS + tx*4];
            #pragma unroll
            for (int i = 0; i < 8; i++) {
                float4 p4 = *(const float4*)&Ps[(ty*8 + i)*PS + tt*4];
                o[i][0] = fmaf(p4.x, v0.x, fmaf(p4.y, v1.x, fmaf(p4.z, v2.x, fmaf(p4.w, v3.x, o[i][0]))));
                o[i][1] = fmaf(p4.x, v0.y, fmaf(p4.y, v1.y, fmaf(p4.z, v2.y, fmaf(p4.w, v3.y, o[i][1]))));
                o[i][2] = fmaf(p4.x, v0.z, fmaf(p4.y, v1.z, fmaf(p4.z, v2.z, fmaf(p4.w, v3.z, o[i][2]))));
                o[i][3] = fmaf(p4.x, v0.w, fmaf(p4.y, v1.w, fmaf(p4.z, v2.w, fmaf(p4.w, v3.w, o[i][3]))));
            }
        }
        __syncthreads();
    }

    // epilogue: out = o/l - 1e9*pv  -> g_attn [n*s][h*64+dd]
    const int n  = nh >> 4;
    const int hh = nh & 15;
    #pragma unroll
    for (int i = 0; i < 8; i++) {
        int s = q0 + ty*8 + i;
        float inv = 1.0f / l[i];
        float4 pv4 = *(const float4*)(g_pv + ((size_t)nh * SEQ + s) * HD + tx*4);
        float4 r;
        r.x = o[i][0] * inv - NEGC * pv4.x;
        r.y = o[i][1] * inv - NEGC * pv4.y;
        r.z = o[i][2] * inv - NEGC * pv4.z;
        r.w = o[i][3] * inv - NEGC * pv4.w;
        *(float4*)(g_attn + ((size_t)(n * SEQ + s)) * DIM + hh * HD + tx*4) = r;
    }
}

// ---------------------------------------------------------------------------
// Kernel 4: output projection  out = g_attn @ wo^T + bo. grid (8, 64)
// ---------------------------------------------------------------------------
__global__ void __launch_bounds__(256) gemm_out_kernel(
    const float* __restrict__ wo,
    const float* __restrict__ bo,
    float* __restrict__ out)
{
    __shared__ float As[8*TSTR];
    __shared__ float Bs[8*TSTR];

    const int row0 = blockIdx.y * 128;
    const int col0 = blockIdx.x * 128;
    float acc[8][8] = {};

    sgemm_core(g_attn, wo, row0, col0, As, Bs, acc);

    const int tx = threadIdx.x & 15, ty = threadIdx.x >> 4;
    const int c0 = col0 + tx * 8;
    float4 b0 = *(const float4*)(bo + c0);
    float4 b1 = *(const float4*)(bo + c0 + 4);
    #pragma unroll
    for (int i = 0; i < 8; i++) {
        int r = row0 + ty*8 + i;
        float4 v0 = {acc[i][0]+b0.x, acc[i][1]+b0.y, acc[i][2]+b0.z, acc[i][3]+b0.w};
        float4 v1 = {acc[i][4]+b1.x, acc[i][5]+b1.y, acc[i][6]+b1.z, acc[i][7]+b1.w};
        *(float4*)(out + (size_t)r * DIM + c0)     = v0;
        *(float4*)(out + (size_t)r * DIM + c0 + 4) = v1;
    }
}

// ---------------------------------------------------------------------------
extern "C" void kernel_launch(void* const* d_in, const int* in_sizes, int n_in,
                              void* d_out, int out_size)
{
    const float* x  = (const float*)d_in[0];
    const float* wq = (const float*)d_in[1];
    const float* wk = (const float*)d_in[2];
    const float* wv = (const float*)d_in[3];
    const float* wo = (const float*)d_in[4];
    const float* bo = (const float*)d_in[5];
    float* out = (float*)d_out;

    cudaFuncSetAttribute(attn_kernel,
                         cudaFuncAttributeMaxDynamicSharedMemorySize, ATTN_SMEM);

    gemm_qkv_kernel<<<dim3(DIM/128, NS/128, 3), 256>>>(x, wq, wk, wv);
    prefix_kernel<<<NH, HD>>>();
    attn_kernel<<<dim3(SEQ/128, NH), 256, ATTN_SMEM>>>();
    gemm_out_kernel<<<dim3(DIM/128, NS/128), 256>>>(wo, bo, out);
}

// round 4
// speedup vs baseline: 6.5137x; 4.8169x over previous
#include <cuda_runtime.h>
#include <cuda_bf16.h>
#include <cstdint>

// Problem constants
#define NB    4
#define SEQ   2048
#define DIM   1024
#define HEADS 16
#define HD    64
#define NS    (NB*SEQ)          // 8192
#define NH    (NB*HEADS)        // 64
#define NEGC  1000000000.0f

// ---------------------------------------------------------------------------
// Scratch (device globals)
// ---------------------------------------------------------------------------
__device__ __align__(16) float g_v [(size_t)NH * SEQ * HD];          // V fp32 (for prefix)
__device__ __align__(16) float g_pv[(size_t)NH * SEQ * HD];          // exclusive prefix of V
__device__ __align__(16) float g_psum[NH][8][HD];
__device__ __align__(16) __nv_bfloat16 g_qb[(size_t)NH * SEQ * HD];  // Q*0.125 bf16
__device__ __align__(16) __nv_bfloat16 g_kb[(size_t)NH * SEQ * HD];  // K bf16
__device__ __align__(16) __nv_bfloat16 g_vb[(size_t)NH * SEQ * HD];  // V bf16
__device__ __align__(16) __nv_bfloat16 g_xh[(size_t)NS * DIM];
__device__ __align__(16) __nv_bfloat16 g_xl[(size_t)NS * DIM];
__device__ __align__(16) __nv_bfloat16 g_ah[(size_t)NS * DIM];       // attn out hi
__device__ __align__(16) __nv_bfloat16 g_al[(size_t)NS * DIM];       // attn out lo
__device__ __align__(16) __nv_bfloat16 g_wh[(size_t)4 * DIM * DIM];  // wq,wk,wv,wo hi
__device__ __align__(16) __nv_bfloat16 g_wl[(size_t)4 * DIM * DIM];  // lo

// ---------------------------------------------------------------------------
// PTX helpers (sm_103 base target: ldmatrix + mma.sync only)
// ---------------------------------------------------------------------------
__device__ __forceinline__ uint32_t smem_to_u32(const void* p) {
    uint32_t a;
    asm("{ .reg .u64 t; cvta.to.shared.u64 t, %1; cvt.u32.u64 %0, t; }"
        : "=r"(a) : "l"(p));
    return a;
}

#define LDSM_X4(r, addr) \
    asm volatile("ldmatrix.sync.aligned.m8n8.x4.shared.b16 {%0,%1,%2,%3}, [%4];" \
        : "=r"((r)[0]), "=r"((r)[1]), "=r"((r)[2]), "=r"((r)[3]) : "r"(addr))

#define LDSM_X4_T(r, addr) \
    asm volatile("ldmatrix.sync.aligned.m8n8.x4.trans.shared.b16 {%0,%1,%2,%3}, [%4];" \
        : "=r"((r)[0]), "=r"((r)[1]), "=r"((r)[2]), "=r"((r)[3]) : "r"(addr))

#define MMA_BF16(c, a, b0, b1) \
    asm volatile("mma.sync.aligned.m16n8k16.row.col.f32.bf16.bf16.f32 " \
        "{%0,%1,%2,%3}, {%4,%5,%6,%7}, {%8,%9}, {%0,%1,%2,%3};" \
        : "+f"((c)[0]), "+f"((c)[1]), "+f"((c)[2]), "+f"((c)[3]) \
        : "r"((a)[0]), "r"((a)[1]), "r"((a)[2]), "r"((a)[3]), "r"(b0), "r"(b1))

__device__ __forceinline__ uint32_t packbf2(float lo, float hi) {
    __nv_bfloat162 t = __floats2bfloat162_rn(lo, hi);
    return *reinterpret_cast<uint32_t*>(&t);
}

// ---------------------------------------------------------------------------
// bf16 split kernels:  x = hi + lo
// ---------------------------------------------------------------------------
__device__ __forceinline__ void split4(float4 v, __nv_bfloat16* h, __nv_bfloat16* l)
{
    h[0] = __float2bfloat16(v.x); l[0] = __float2bfloat16(v.x - __bfloat162float(h[0]));
    h[1] = __float2bfloat16(v.y); l[1] = __float2bfloat16(v.y - __bfloat162float(h[1]));
    h[2] = __float2bfloat16(v.z); l[2] = __float2bfloat16(v.z - __bfloat162float(h[2]));
    h[3] = __float2bfloat16(v.w); l[3] = __float2bfloat16(v.w - __bfloat162float(h[3]));
}

__global__ void __launch_bounds__(256) split_x_kernel(const float* __restrict__ x)
{
    size_t i = ((size_t)blockIdx.x * 256 + threadIdx.x) * 4;
    float4 v = *(const float4*)(x + i);
    __nv_bfloat16 h[4], l[4];
    split4(v, h, l);
    *(uint2*)(g_xh + i) = *(uint2*)h;
    *(uint2*)(g_xl + i) = *(uint2*)l;
}

__global__ void __launch_bounds__(256) split_w_kernel(
    const float* __restrict__ wq, const float* __restrict__ wk,
    const float* __restrict__ wv, const float* __restrict__ wo)
{
    const float* w = (blockIdx.y == 0) ? wq : (blockIdx.y == 1) ? wk
                   : (blockIdx.y == 2) ? wv : wo;
    size_t base = (size_t)blockIdx.y * DIM * DIM;
    size_t i = ((size_t)blockIdx.x * 256 + threadIdx.x) * 4;
    float4 v = *(const float4*)(w + i);
    __nv_bfloat16 h[4], l[4];
    split4(v, h, l);
    *(uint2*)(g_wh + base + i) = *(uint2*)h;
    *(uint2*)(g_wl + base + i) = *(uint2*)l;
}

// ---------------------------------------------------------------------------
// mma.sync GEMM core: C(128x128) = A(128x1024) @ B(128x1024)^T
// 256 threads = 8 warps (2m x 4n), warp tile 64x32, BK=32, smem pitch 40 bf16.
// X3: 3-product bf16 hi/lo split for full fp32-like accuracy.
// ---------------------------------------------------------------------------
#define PGP 40   // projection smem pitch (bf16 units)

template<bool X3>
__device__ __forceinline__ void gemm128(
    const __nv_bfloat16* __restrict__ Agh, const __nv_bfloat16* __restrict__ Agl,
    const __nv_bfloat16* __restrict__ Bgh, const __nv_bfloat16* __restrict__ Bgl,
    int row0, int col0,
    __nv_bfloat16* sAh, __nv_bfloat16* sAl,
    __nv_bfloat16* sBh, __nv_bfloat16* sBl,
    float acc[4][4][4])
{
    const int tid = threadIdx.x, lane = tid & 31, wid = tid >> 5;
    const int warp_m = (wid >> 2) * 64, warp_n = (wid & 3) * 32;
    const uint32_t ah_b = smem_to_u32(sAh), bh_b = smem_to_u32(sBh);
    uint32_t al_b = 0, bl_b = 0;
    if (X3) { al_b = smem_to_u32(sAl); bl_b = smem_to_u32(sBl); }

    uint4 pah[2], pbh[2], pal[2], pbl[2];
    #pragma unroll
    for (int i = 0; i < 2; i++) {
        int idx = i*256 + tid; int r = idx >> 2, c = (idx & 3) * 8;
        pah[i] = *(const uint4*)(Agh + (size_t)(row0 + r) * DIM + c);
        pbh[i] = *(const uint4*)(Bgh + (size_t)(col0 + r) * DIM + c);
        if (X3) {
            pal[i] = *(const uint4*)(Agl + (size_t)(row0 + r) * DIM + c);
            pbl[i] = *(const uint4*)(Bgl + (size_t)(col0 + r) * DIM + c);
        }
    }

    for (int kt = 0; kt < DIM/32; kt++) {
        #pragma unroll
        for (int i = 0; i < 2; i++) {
            int idx = i*256 + tid; int r = idx >> 2, c = (idx & 3) * 8;
            *(uint4*)(sAh + r*PGP + c) = pah[i];
            *(uint4*)(sBh + r*PGP + c) = pbh[i];
            if (X3) {
                *(uint4*)(sAl + r*PGP + c) = pal[i];
                *(uint4*)(sBl + r*PGP + c) = pbl[i];
            }
        }
        __syncthreads();

        if (kt + 1 < DIM/32) {
            int koff = (kt + 1) * 32;
            #pragma unroll
            for (int i = 0; i < 2; i++) {
                int idx = i*256 + tid; int r = idx >> 2, c = (idx & 3) * 8;
                pah[i] = *(const uint4*)(Agh + (size_t)(row0 + r) * DIM + koff + c);
                pbh[i] = *(const uint4*)(Bgh + (size_t)(col0 + r) * DIM + koff + c);
                if (X3) {
                    pal[i] = *(const uint4*)(Agl + (size_t)(row0 + r) * DIM + koff + c);
                    pbl[i] = *(const uint4*)(Bgl + (size_t)(col0 + r) * DIM + koff + c);
                }
            }
        }

        #pragma unroll
        for (int ks = 0; ks < 2; ks++) {
            uint32_t af[4][4], bfh[2][4];
            #pragma unroll
            for (int mt = 0; mt < 4; mt++) {
                uint32_t ad = ah_b + (uint32_t)(((warp_m + mt*16 + (lane&15))*PGP + ks*16)*2 + (lane&16));
                LDSM_X4(af[mt], ad);
            }
            #pragma unroll
            for (int p = 0; p < 2; p++) {
                uint32_t bd = bh_b + (uint32_t)(((warp_n + p*16 + (lane&7) + ((lane&16)>>1))*PGP + ks*16)*2 + ((lane&8)<<1));
                LDSM_X4(bfh[p], bd);
            }
            #pragma unroll
            for (int mt = 0; mt < 4; mt++)
                #pragma unroll
                for (int p = 0; p < 2; p++) {
                    MMA_BF16(acc[mt][2*p],   af[mt], bfh[p][0], bfh[p][1]);
                    MMA_BF16(acc[mt][2*p+1], af[mt], bfh[p][2], bfh[p][3]);
                }
            if (X3) {
                uint32_t alf[4][4], blf[2][4];
                #pragma unroll
                for (int mt = 0; mt < 4; mt++) {
                    uint32_t ad = al_b + (uint32_t)(((warp_m + mt*16 + (lane&15))*PGP + ks*16)*2 + (lane&16));
                    LDSM_X4(alf[mt], ad);
                }
                #pragma unroll
                for (int p = 0; p < 2; p++) {
                    uint32_t bd = bl_b + (uint32_t)(((warp_n + p*16 + (lane&7) + ((lane&16)>>1))*PGP + ks*16)*2 + ((lane&8)<<1));
                    LDSM_X4(blf[p], bd);
                }
                #pragma unroll
                for (int mt = 0; mt < 4; mt++)
                    #pragma unroll
                    for (int p = 0; p < 2; p++) {
                        MMA_BF16(acc[mt][2*p],   af[mt],  blf[p][0], blf[p][1]);
                        MMA_BF16(acc[mt][2*p+1], af[mt],  blf[p][2], blf[p][3]);
                        MMA_BF16(acc[mt][2*p],   alf[mt], bfh[p][0], bfh[p][1]);
                        MMA_BF16(acc[mt][2*p+1], alf[mt], bfh[p][2], bfh[p][3]);
                    }
            }
        }
        __syncthreads();
    }
}

// ---------------------------------------------------------------------------
// Q/K projection (plain bf16, x1). grid (8, 64, 2). Q folded scale 0.125.
// ---------------------------------------------------------------------------
__global__ void __launch_bounds__(256) proj_qk_kernel()
{
    __shared__ __nv_bfloat16 sA[128*PGP];
    __shared__ __nv_bfloat16 sB[128*PGP];
    const int z = blockIdx.z;
    const __nv_bfloat16* Bh = g_wh + (size_t)z * DIM * DIM;
    __nv_bfloat16* dst = z ? g_kb : g_qb;
    const float scale = z ? 1.0f : 0.125f;
    const int row0 = blockIdx.y * 128, col0 = blockIdx.x * 128;

    float acc[4][4][4] = {};
    gemm128<false>(g_xh, nullptr, Bh, nullptr, row0, col0, sA, nullptr, sB, nullptr, acc);

    const int lane = threadIdx.x & 31, wid = threadIdx.x >> 5;
    const int warp_m = (wid >> 2) * 64, warp_n = (wid & 3) * 32;
    #pragma unroll
    for (int mt = 0; mt < 4; mt++) {
        int r0 = row0 + warp_m + mt*16 + (lane >> 2);
        #pragma unroll
        for (int nt = 0; nt < 4; nt++) {
            int col = col0 + warp_n + nt*8 + (lane & 3) * 2;
            int h = col >> 6, dd = col & 63;
            #pragma unroll
            for (int half = 0; half < 2; half++) {
                int r = r0 + half*8;
                int n = r >> 11, s = r & (SEQ - 1);
                __nv_bfloat162 hv = __floats2bfloat162_rn(acc[mt][nt][2*half]*scale,
                                                          acc[mt][nt][2*half+1]*scale);
                *(__nv_bfloat162*)(dst + (((size_t)(n*HEADS + h)*SEQ + s))*HD + dd) = hv;
            }
        }
    }
}

// ---------------------------------------------------------------------------
// V projection (x3 split). grid (8, 64). Writes fp32 g_v + bf16 g_vb.
// ---------------------------------------------------------------------------
__global__ void __launch_bounds__(256) proj_v_kernel()
{
    __shared__ __nv_bfloat16 sAh[128*PGP], sAl[128*PGP];
    __shared__ __nv_bfloat16 sBh[128*PGP], sBl[128*PGP];
    const __nv_bfloat16* Bh = g_wh + (size_t)2 * DIM * DIM;
    const __nv_bfloat16* Bl = g_wl + (size_t)2 * DIM * DIM;
    const int row0 = blockIdx.y * 128, col0 = blockIdx.x * 128;

    float acc[4][4][4] = {};
    gemm128<true>(g_xh, g_xl, Bh, Bl, row0, col0, sAh, sAl, sBh, sBl, acc);

    const int lane = threadIdx.x & 31, wid = threadIdx.x >> 5;
    const int warp_m = (wid >> 2) * 64, warp_n = (wid & 3) * 32;
    #pragma unroll
    for (int mt = 0; mt < 4; mt++) {
        int r0 = row0 + warp_m + mt*16 + (lane >> 2);
        #pragma unroll
        for (int nt = 0; nt < 4; nt++) {
            int col = col0 + warp_n + nt*8 + (lane & 3) * 2;
            int h = col >> 6, dd = col & 63;
            #pragma unroll
            for (int half = 0; half < 2; half++) {
                int r = r0 + half*8;
                int n = r >> 11, s = r & (SEQ - 1);
                float vx = acc[mt][nt][2*half], vy = acc[mt][nt][2*half+1];
                size_t off = (((size_t)(n*HEADS + h)*SEQ + s))*HD + dd;
                float2 f2 = {vx, vy};
                *(float2*)(g_v + off) = f2;
                *(__nv_bfloat162*)(g_vb + off) = __floats2bfloat162_rn(vx, vy);
            }
        }
    }
}

// ---------------------------------------------------------------------------
// Output projection (x3) + bias. grid (8, 64).
// ---------------------------------------------------------------------------
__global__ void __launch_bounds__(256) proj_out_kernel(
    const float* __restrict__ bo, float* __restrict__ out)
{
    __shared__ __nv_bfloat16 sAh[128*PGP], sAl[128*PGP];
    __shared__ __nv_bfloat16 sBh[128*PGP], sBl[128*PGP];
    const __nv_bfloat16* Bh = g_wh + (size_t)3 * DIM * DIM;
    const __nv_bfloat16* Bl = g_wl + (size_t)3 * DIM * DIM;
    const int row0 = blockIdx.y * 128, col0 = blockIdx.x * 128;

    float acc[4][4][4] = {};
    gemm128<true>(g_ah, g_al, Bh, Bl, row0, col0, sAh, sAl, sBh, sBl, acc);

    const int lane = threadIdx.x & 31, wid = threadIdx.x >> 5;
    const int warp_m = (wid >> 2) * 64, warp_n = (wid & 3) * 32;
    #pragma unroll
    for (int mt = 0; mt < 4; mt++) {
        int r0 = row0 + warp_m + mt*16 + (lane >> 2);
        #pragma unroll
        for (int nt = 0; nt < 4; nt++) {
            int col = col0 + warp_n + nt*8 + (lane & 3) * 2;
            float2 bb = *(const float2*)(bo + col);
            #pragma unroll
            for (int half = 0; half < 2; half++) {
                int r = r0 + half*8;
                float2 f2 = {acc[mt][nt][2*half] + bb.x, acc[mt][nt][2*half+1] + bb.y};
                *(float2*)(out + (size_t)r * DIM + col) = f2;
            }
        }
    }
}

// ---------------------------------------------------------------------------
// Exclusive prefix sum of V (two-pass, 8 chunks of 256).
// ---------------------------------------------------------------------------
__global__ void prefix_a_kernel()   // grid (NH, 8), block 64
{
    const int nh = blockIdx.x, sc = blockIdx.y, dd = threadIdx.x;
    const float* v = g_v + ((size_t)nh * SEQ + sc * 256) * HD + dd;
    float s = 0.0f;
    for (int t = 0; t < 256; t++) s += v[(size_t)t * HD];
    g_psum[nh][sc][dd] = s;
}
__global__ void prefix_b_kernel()   // grid (NH, 8), block 64
{
    const int nh = blockIdx.x, sc = blockIdx.y, dd = threadIdx.x;
    float run = 0.0f;
    for (int c = 0; c < sc; c++) run += g_psum[nh][c][dd];
    const float* v  = g_v  + ((size_t)nh * SEQ + sc * 256) * HD + dd;
    float*       pv = g_pv + ((size_t)nh * SEQ + sc * 256) * HD + dd;
    for (int t = 0; t < 256; t++) {
        pv[(size_t)t * HD] = run;
        run += v[(size_t)t * HD];
    }
}

// ---------------------------------------------------------------------------
// Flash attention on mma.sync (no mask in softmax) + post-softmax correction:
//   out = softmax(QK^T/8) @ V - 1e9 * prefixsum(V)
// BM=128 (8 warps x m16), BN=64, bf16 HMMA, epilogue splits to bf16 hi/lo.
// grid (16, 64), 256 threads.
// ---------------------------------------------------------------------------
#define AP 72   // attention smem pitch (bf16 units), 144B rows

__global__ void __launch_bounds__(256) attn_kernel()
{
    __shared__ __nv_bfloat16 Qs[128*AP];
    __shared__ __nv_bfloat16 Ks[64*AP];
    __shared__ __nv_bfloat16 Vs[64*AP];

    const int tid = threadIdx.x, lane = tid & 31, wid = tid >> 5;
    const int nh = blockIdx.y, q0 = blockIdx.x * 128;
    const __nv_bfloat16* qg = g_qb + (size_t)nh * SEQ * HD;
    const __nv_bfloat16* kg = g_kb + (size_t)nh * SEQ * HD;
    const __nv_bfloat16* vg = g_vb + (size_t)nh * SEQ * HD;
    const uint32_t qs_b = smem_to_u32(Qs), ks_b = smem_to_u32(Ks), vs_b = smem_to_u32(Vs);

    // stage Q tile, load persistent Q fragments (m16 x k64 per warp)
    #pragma unroll
    for (int i = 0; i < 4; i++) {
        int idx = i*256 + tid; int r = idx >> 3, c = (idx & 7) * 8;
        *(uint4*)(Qs + r*AP + c) = *(const uint4*)(qg + (size_t)(q0 + r) * HD + c);
    }
    __syncthreads();
    uint32_t qf[4][4];
    const int m0 = wid * 16;
    #pragma unroll
    for (int ks = 0; ks < 4; ks++) {
        uint32_t ad = qs_b + (uint32_t)(((m0 + (lane&15))*AP + ks*16)*2 + (lane&16));
        LDSM_X4(qf[ks], ad);
    }

    float o[8][4] = {};
    float mr0 = -1e30f, mr1 = -1e30f, lr0 = 0.0f, lr1 = 0.0f;

    uint4 kr[2], vr[2];
    #pragma unroll
    for (int i = 0; i < 2; i++) {
        int idx = i*256 + tid; int r = idx >> 3, c = (idx & 7) * 8;
        kr[i] = *(const uint4*)(kg + (size_t)r * HD + c);
        vr[i] = *(const uint4*)(vg + (size_t)r * HD + c);
    }

    for (int kt = 0; kt < SEQ/64; kt++) {
        #pragma unroll
        for (int i = 0; i < 2; i++) {
            int idx = i*256 + tid; int r = idx >> 3, c = (idx & 7) * 8;
            *(uint4*)(Ks + r*AP + c) = kr[i];
            *(uint4*)(Vs + r*AP + c) = vr[i];
        }
        __syncthreads();
        if (kt + 1 < SEQ/64) {
            #pragma unroll
            for (int i = 0; i < 2; i++) {
                int idx = i*256 + tid; int r = idx >> 3, c = (idx & 7) * 8;
                kr[i] = *(const uint4*)(kg + (size_t)((kt+1)*64 + r) * HD + c);
                vr[i] = *(const uint4*)(vg + (size_t)((kt+1)*64 + r) * HD + c);
            }
        }

        // S = Q K^T : 8 n-tiles (64 keys), k = 64 (4 ksteps)
        float sf[8][4] = {};
        #pragma unroll
        for (int ks = 0; ks < 4; ks++) {
            uint32_t bfr[4][4];
            #pragma unroll
            for (int p = 0; p < 4; p++) {
                uint32_t bd = ks_b + (uint32_t)(((p*16 + (lane&7) + ((lane&16)>>1))*AP + ks*16)*2 + ((lane&8)<<1));
                LDSM_X4(bfr[p], bd);
            }
            #pragma unroll
            for (int p = 0; p < 4; p++) {
                MMA_BF16(sf[2*p],   qf[ks], bfr[p][0], bfr[p][1]);
                MMA_BF16(sf[2*p+1], qf[ks], bfr[p][2], bfr[p][3]);
            }
        }

        // online softmax: thread owns 2 rows (lane/4, +8), 16 cols each
        float mx0 = -1e30f, mx1 = -1e30f;
        #pragma unroll
        for (int nt = 0; nt < 8; nt++) {
            mx0 = fmaxf(mx0, fmaxf(sf[nt][0], sf[nt][1]));
            mx1 = fmaxf(mx1, fmaxf(sf[nt][2], sf[nt][3]));
        }
        mx0 = fmaxf(mx0, __shfl_xor_sync(0xffffffffu, mx0, 1));
        mx0 = fmaxf(mx0, __shfl_xor_sync(0xffffffffu, mx0, 2));
        mx1 = fmaxf(mx1, __shfl_xor_sync(0xffffffffu, mx1, 1));
        mx1 = fmaxf(mx1, __shfl_xor_sync(0xffffffffu, mx1, 2));
        float mn0 = fmaxf(mr0, mx0), mn1 = fmaxf(mr1, mx1);
        float c0 = __expf(mr0 - mn0), c1 = __expf(mr1 - mn1);
        mr0 = mn0; mr1 = mn1;

        uint32_t pf[4][4];
        float s0 = 0.0f, s1 = 0.0f;
        #pragma unroll
        for (int g = 0; g < 4; g++) {
            float e00 = __expf(sf[2*g][0]   - mn0), e01 = __expf(sf[2*g][1]   - mn0);
            float e02 = __expf(sf[2*g][2]   - mn1), e03 = __expf(sf[2*g][3]   - mn1);
            float e10 = __expf(sf[2*g+1][0] - mn0), e11 = __expf(sf[2*g+1][1] - mn0);
            float e12 = __expf(sf[2*g+1][2] - mn1), e13 = __expf(sf[2*g+1][3] - mn1);
            s0 += (e00 + e01) + (e10 + e11);
            s1 += (e02 + e03) + (e12 + e13);
            pf[g][0] = packbf2(e00, e01);
            pf[g][1] = packbf2(e02, e03);
            pf[g][2] = packbf2(e10, e11);
            pf[g][3] = packbf2(e12, e13);
        }
        s0 += __shfl_xor_sync(0xffffffffu, s0, 1);
        s0 += __shfl_xor_sync(0xffffffffu, s0, 2);
        s1 += __shfl_xor_sync(0xffffffffu, s1, 1);
        s1 += __shfl_xor_sync(0xffffffffu, s1, 2);
        lr0 = lr0 * c0 + s0;
        lr1 = lr1 * c1 + s1;
        #pragma unroll
        for (int nt = 0; nt < 8; nt++) {
            o[nt][0] *= c0; o[nt][1] *= c0;
            o[nt][2] *= c1; o[nt][3] *= c1;
        }

        // O += P @ V : dd 64 (8 n-tiles), k = 64 keys (4 ksteps), V via ldmatrix.trans
        #pragma unroll
        for (int g = 0; g < 4; g++) {
            uint32_t vf[4][4];
            #pragma unroll
            for (int p = 0; p < 4; p++) {
                uint32_t vd = vs_b + (uint32_t)(((g*16 + (lane&7) + (lane&8))*AP + p*16)*2 + (lane&16));
                LDSM_X4_T(vf[p], vd);
            }
            #pragma unroll
            for (int p = 0; p < 4; p++) {
                MMA_BF16(o[2*p],   pf[g], vf[p][0], vf[p][1]);
                MMA_BF16(o[2*p+1], pf[g], vf[p][2], vf[p][3]);
            }
        }
        __syncthreads();
    }

    // epilogue: r = o/l - 1e9*pv; bf16 hi/lo split -> g_ah/g_al [n*s][h*64+dd]
    const int n = nh >> 4, hh = nh & 15;
    const int srow0 = q0 + m0 + (lane >> 2);
    const float i0 = 1.0f / lr0, i1 = 1.0f / lr1;
    #pragma unroll
    for (int nt = 0; nt < 8; nt++) {
        int dd = nt*8 + (lane & 3) * 2;
        #pragma unroll
        for (int half = 0; half < 2; half++) {
            int s = srow0 + half*8;
            float inv = half ? i1 : i0;
            float2 pv = *(const float2*)(g_pv + ((size_t)nh * SEQ + s) * HD + dd);
            float rx = o[nt][2*half]   * inv - NEGC * pv.x;
            float ry = o[nt][2*half+1] * inv - NEGC * pv.y;
            __nv_bfloat16 hx = __float2bfloat16(rx);
            __nv_bfloat16 hy = __float2bfloat16(ry);
            __nv_bfloat16 lx = __float2bfloat16(rx - __bfloat162float(hx));
            __nv_bfloat16 ly = __float2bfloat16(ry - __bfloat162float(hy));
            size_t off = ((size_t)(n * SEQ + s)) * DIM + hh * HD + dd;
            __nv_bfloat162 hv; hv.x = hx; hv.y = hy;
            __nv_bfloat162 lv; lv.x = lx; lv.y = ly;
            *(__nv_bfloat162*)(g_ah + off) = hv;
            *(__nv_bfloat162*)(g_al + off) = lv;
        }
    }
}

// ---------------------------------------------------------------------------
extern "C" void kernel_launch(void* const* d_in, const int* in_sizes, int n_in,
                              void* d_out, int out_size)
{
    const float* x  = (const float*)d_in[0];
    const float* wq = (const float*)d_in[1];
    const float* wk = (const float*)d_in[2];
    const float* wv = (const float*)d_in[3];
    const float* wo = (const float*)d_in[4];
    const float* bo = (const float*)d_in[5];
    float* out = (float*)d_out;

    split_x_kernel<<<NS*DIM/(256*4), 256>>>(x);
    split_w_kernel<<<dim3(DIM*DIM/(256*4), 4), 256>>>(wq, wk, wv, wo);
    proj_qk_kernel<<<dim3(DIM/128, NS/128, 2), 256>>>();
    proj_v_kernel<<<dim3(DIM/128, NS/128), 256>>>();
    prefix_a_kernel<<<dim3(NH, 8), HD>>>();
    prefix_b_kernel<<<dim3(NH, 8), HD>>>();
    attn_kernel<<<dim3(SEQ/128, NH), 256>>>();
    proj_out_kernel<<<dim3(DIM/128, NS/128), 256>>>(bo, out);
}

// round 5
// speedup vs baseline: 7.0347x; 1.0800x over previous
#include <cuda_runtime.h>
#include <cuda_bf16.h>
#include <cstdint>

// Problem constants
#define NB    4
#define SEQ   2048
#define DIM   1024
#define HEADS 16
#define HD    64
#define NS    (NB*SEQ)          // 8192
#define NH    (NB*HEADS)        // 64
#define NEGC  1000000000.0f

// ---------------------------------------------------------------------------
// Scratch (device globals)
// ---------------------------------------------------------------------------
__device__ __align__(16) float g_v [(size_t)NH * SEQ * HD];          // V fp32 (for prefix)
__device__ __align__(16) float g_pv[(size_t)NH * SEQ * HD];          // exclusive prefix of V
__device__ __align__(16) float g_psum[NH][8][HD];
__device__ __align__(16) __nv_bfloat16 g_qb[(size_t)NH * SEQ * HD];  // Q*0.125 bf16
__device__ __align__(16) __nv_bfloat16 g_kb[(size_t)NH * SEQ * HD];  // K bf16
__device__ __align__(16) __nv_bfloat16 g_vb[(size_t)NH * SEQ * HD];  // V bf16
__device__ __align__(16) __nv_bfloat16 g_xh[(size_t)NS * DIM];
__device__ __align__(16) __nv_bfloat16 g_xl[(size_t)NS * DIM];
__device__ __align__(16) __nv_bfloat16 g_ah[(size_t)NS * DIM];       // attn out hi
__device__ __align__(16) __nv_bfloat16 g_al[(size_t)NS * DIM];       // attn out lo
__device__ __align__(16) __nv_bfloat16 g_wh[(size_t)4 * DIM * DIM];  // wq,wk,wv,wo hi
__device__ __align__(16) __nv_bfloat16 g_wl[(size_t)4 * DIM * DIM];  // lo

// ---------------------------------------------------------------------------
// PTX helpers (base sm_103: ldmatrix + mma.sync + cp.async)
// ---------------------------------------------------------------------------
__device__ __forceinline__ uint32_t smem_to_u32(const void* p) {
    uint32_t a;
    asm("{ .reg .u64 t; cvta.to.shared.u64 t, %1; cvt.u32.u64 %0, t; }"
        : "=r"(a) : "l"(p));
    return a;
}

#define CP16(dst, src) \
    asm volatile("cp.async.cg.shared.global [%0], [%1], 16;" \
                 :: "r"((uint32_t)(dst)), "l"(src))
#define CP_COMMIT() asm volatile("cp.async.commit_group;" ::: "memory")
#define CP_WAIT0()  asm volatile("cp.async.wait_group 0;" ::: "memory")

#define LDSM_X4(r, addr) \
    asm volatile("ldmatrix.sync.aligned.m8n8.x4.shared.b16 {%0,%1,%2,%3}, [%4];" \
        : "=r"((r)[0]), "=r"((r)[1]), "=r"((r)[2]), "=r"((r)[3]) : "r"(addr))

#define LDSM_X4_T(r, addr) \
    asm volatile("ldmatrix.sync.aligned.m8n8.x4.trans.shared.b16 {%0,%1,%2,%3}, [%4];" \
        : "=r"((r)[0]), "=r"((r)[1]), "=r"((r)[2]), "=r"((r)[3]) : "r"(addr))

#define MMA_BF16(c, a, b0, b1) \
    asm volatile("mma.sync.aligned.m16n8k16.row.col.f32.bf16.bf16.f32 " \
        "{%0,%1,%2,%3}, {%4,%5,%6,%7}, {%8,%9}, {%0,%1,%2,%3};" \
        : "+f"((c)[0]), "+f"((c)[1]), "+f"((c)[2]), "+f"((c)[3]) \
        : "r"((a)[0]), "r"((a)[1]), "r"((a)[2]), "r"((a)[3]), "r"(b0), "r"(b1))

__device__ __forceinline__ uint32_t packbf2(float lo, float hi) {
    __nv_bfloat162 t = __floats2bfloat162_rn(lo, hi);
    return *reinterpret_cast<uint32_t*>(&t);
}

// ---------------------------------------------------------------------------
// bf16 split kernels:  x = hi + lo
// ---------------------------------------------------------------------------
__device__ __forceinline__ void split4(float4 v, __nv_bfloat16* h, __nv_bfloat16* l)
{
    h[0] = __float2bfloat16(v.x); l[0] = __float2bfloat16(v.x - __bfloat162float(h[0]));
    h[1] = __float2bfloat16(v.y); l[1] = __float2bfloat16(v.y - __bfloat162float(h[1]));
    h[2] = __float2bfloat16(v.z); l[2] = __float2bfloat16(v.z - __bfloat162float(h[2]));
    h[3] = __float2bfloat16(v.w); l[3] = __float2bfloat16(v.w - __bfloat162float(h[3]));
}

__global__ void __launch_bounds__(256) split_x_kernel(const float* __restrict__ x)
{
    size_t i = ((size_t)blockIdx.x * 256 + threadIdx.x) * 4;
    float4 v = *(const float4*)(x + i);
    __nv_bfloat16 h[4], l[4];
    split4(v, h, l);
    *(uint2*)(g_xh + i) = *(uint2*)h;
    *(uint2*)(g_xl + i) = *(uint2*)l;
}

__global__ void __launch_bounds__(256) split_w_kernel(
    const float* __restrict__ wq, const float* __restrict__ wk,
    const float* __restrict__ wv, const float* __restrict__ wo)
{
    const float* w = (blockIdx.y == 0) ? wq : (blockIdx.y == 1) ? wk
                   : (blockIdx.y == 2) ? wv : wo;
    size_t base = (size_t)blockIdx.y * DIM * DIM;
    size_t i = ((size_t)blockIdx.x * 256 + threadIdx.x) * 4;
    float4 v = *(const float4*)(w + i);
    __nv_bfloat16 h[4], l[4];
    split4(v, h, l);
    *(uint2*)(g_wh + base + i) = *(uint2*)h;
    *(uint2*)(g_wl + base + i) = *(uint2*)l;
}

// ---------------------------------------------------------------------------
// cp.async-pipelined mma.sync GEMM core: C(128x128) = A(128x1024) @ B(128x1024)^T
// 256 threads = 8 warps (2m x 4n), warp tile 64x32, BK=32.
// 2-stage ping-pong, ONE __syncthreads per BK-tile.
// X3: 3-product bf16 hi/lo split (AhBh + AhBl + AlBh).
// ---------------------------------------------------------------------------
#define PGP   40                 // smem pitch (bf16 units), 80B rows
#define TILEB (128*PGP*2)        // 10240 B per 128x32 tile

template<bool X3>
__device__ __forceinline__ void gemm128_pipe(
    const __nv_bfloat16* __restrict__ Agh, const __nv_bfloat16* __restrict__ Agl,
    const __nv_bfloat16* __restrict__ Bgh, const __nv_bfloat16* __restrict__ Bgl,
    int row0, int col0, uint32_t sm, float acc[4][4][4])
{
    const int tid = threadIdx.x, lane = tid & 31, wid = tid >> 5;
    const int warp_m = (wid >> 2) * 64, warp_n = (wid & 3) * 32;
    const int STAGE = (X3 ? 4 : 2) * TILEB;
    const int lr = tid >> 2;             // 0..63
    const int lc = (tid & 3) * 8;        // 0,8,16,24
    const uint32_t so1 = (uint32_t)((lr * PGP + lc) * 2);
    const uint32_t so2 = (uint32_t)(((lr + 64) * PGP + lc) * 2);

    auto issue = [&](int kt, int buf) {
        uint32_t base = sm + buf * STAGE;
        const __nv_bfloat16* agh = Agh + (size_t)(row0 + lr) * DIM + kt * 32 + lc;
        const __nv_bfloat16* bgh = Bgh + (size_t)(col0 + lr) * DIM + kt * 32 + lc;
        CP16(base + so1, agh);
        CP16(base + so2, agh + 64 * DIM);
        uint32_t bb = base + (X3 ? 2 : 1) * TILEB;
        CP16(bb + so1, bgh);
        CP16(bb + so2, bgh + 64 * DIM);
        if (X3) {
            const __nv_bfloat16* agl = Agl + (size_t)(row0 + lr) * DIM + kt * 32 + lc;
            const __nv_bfloat16* bgl = Bgl + (size_t)(col0 + lr) * DIM + kt * 32 + lc;
            CP16(base + TILEB + so1, agl);
            CP16(base + TILEB + so2, agl + 64 * DIM);
            CP16(base + 3 * TILEB + so1, bgl);
            CP16(base + 3 * TILEB + so2, bgl + 64 * DIM);
        }
        CP_COMMIT();
    };

    issue(0, 0);

    for (int kt = 0; kt < DIM / 32; kt++) {
        CP_WAIT0();
        __syncthreads();
        if (kt + 1 < DIM / 32) issue(kt + 1, (kt + 1) & 1);

        const uint32_t ah_b = sm + (kt & 1) * STAGE;
        const uint32_t al_b = ah_b + TILEB;
        const uint32_t bh_b = ah_b + (X3 ? 2 : 1) * TILEB;
        const uint32_t bl_b = ah_b + 3 * TILEB;

        #pragma unroll
        for (int ks = 0; ks < 2; ks++) {
            uint32_t af[4][4], bfh[2][4];
            #pragma unroll
            for (int mt = 0; mt < 4; mt++) {
                uint32_t ad = ah_b + (uint32_t)(((warp_m + mt*16 + (lane&15))*PGP + ks*16)*2 + (lane&16));
                LDSM_X4(af[mt], ad);
            }
            #pragma unroll
            for (int p = 0; p < 2; p++) {
                uint32_t bd = bh_b + (uint32_t)(((warp_n + p*16 + (lane&7) + ((lane&16)>>1))*PGP + ks*16)*2 + ((lane&8)<<1));
                LDSM_X4(bfh[p], bd);
            }
            #pragma unroll
            for (int mt = 0; mt < 4; mt++)
                #pragma unroll
                for (int p = 0; p < 2; p++) {
                    MMA_BF16(acc[mt][2*p],   af[mt], bfh[p][0], bfh[p][1]);
                    MMA_BF16(acc[mt][2*p+1], af[mt], bfh[p][2], bfh[p][3]);
                }
            if (X3) {
                uint32_t alf[4][4], blf[2][4];
                #pragma unroll
                for (int mt = 0; mt < 4; mt++) {
                    uint32_t ad = al_b + (uint32_t)(((warp_m + mt*16 + (lane&15))*PGP + ks*16)*2 + (lane&16));
                    LDSM_X4(alf[mt], ad);
                }
                #pragma unroll
                for (int p = 0; p < 2; p++) {
                    uint32_t bd = bl_b + (uint32_t)(((warp_n + p*16 + (lane&7) + ((lane&16)>>1))*PGP + ks*16)*2 + ((lane&8)<<1));
                    LDSM_X4(blf[p], bd);
                }
                #pragma unroll
                for (int mt = 0; mt < 4; mt++)
                    #pragma unroll
                    for (int p = 0; p < 2; p++) {
                        MMA_BF16(acc[mt][2*p],   af[mt],  blf[p][0], blf[p][1]);
                        MMA_BF16(acc[mt][2*p+1], af[mt],  blf[p][2], blf[p][3]);
                        MMA_BF16(acc[mt][2*p],   alf[mt], bfh[p][0], bfh[p][1]);
                        MMA_BF16(acc[mt][2*p+1], alf[mt], bfh[p][2], bfh[p][3]);
                    }
            }
        }
        __syncthreads();   // release smem stage before cp.async of kt+2 overwrites it
    }
}

// ---------------------------------------------------------------------------
// Q/K projection (plain bf16, x1). grid (8, 64, 2). Q folded scale 0.125.
// ---------------------------------------------------------------------------
__global__ void __launch_bounds__(256, 2) proj_qk_kernel()
{
    extern __shared__ char smraw[];
    uint32_t sm = smem_to_u32(smraw);
    const int z = blockIdx.z;
    const __nv_bfloat16* Bh = g_wh + (size_t)z * DIM * DIM;
    __nv_bfloat16* dst = z ? g_kb : g_qb;
    const float scale = z ? 1.0f : 0.125f;
    const int row0 = blockIdx.y * 128, col0 = blockIdx.x * 128;

    float acc[4][4][4] = {};
    gemm128_pipe<false>(g_xh, nullptr, Bh, nullptr, row0, col0, sm, acc);

    const int lane = threadIdx.x & 31, wid = threadIdx.x >> 5;
    const int warp_m = (wid >> 2) * 64, warp_n = (wid & 3) * 32;
    #pragma unroll
    for (int mt = 0; mt < 4; mt++) {
        int r0 = row0 + warp_m + mt*16 + (lane >> 2);
        #pragma unroll
        for (int nt = 0; nt < 4; nt++) {
            int col = col0 + warp_n + nt*8 + (lane & 3) * 2;
            int h = col >> 6, dd = col & 63;
            #pragma unroll
            for (int half = 0; half < 2; half++) {
                int r = r0 + half*8;
                int n = r >> 11, s = r & (SEQ - 1);
                __nv_bfloat162 hv = __floats2bfloat162_rn(acc[mt][nt][2*half]*scale,
                                                          acc[mt][nt][2*half+1]*scale);
                *(__nv_bfloat162*)(dst + (((size_t)(n*HEADS + h)*SEQ + s))*HD + dd) = hv;
            }
        }
    }
}

// ---------------------------------------------------------------------------
// V projection (x3 split). grid (8, 64). Writes fp32 g_v + bf16 g_vb.
// ---------------------------------------------------------------------------
__global__ void __launch_bounds__(256) proj_v_kernel()
{
    extern __shared__ char smraw[];
    uint32_t sm = smem_to_u32(smraw);
    const __nv_bfloat16* Bh = g_wh + (size_t)2 * DIM * DIM;
    const __nv_bfloat16* Bl = g_wl + (size_t)2 * DIM * DIM;
    const int row0 = blockIdx.y * 128, col0 = blockIdx.x * 128;

    float acc[4][4][4] = {};
    gemm128_pipe<true>(g_xh, g_xl, Bh, Bl, row0, col0, sm, acc);

    const int lane = threadIdx.x & 31, wid = threadIdx.x >> 5;
    const int warp_m = (wid >> 2) * 64, warp_n = (wid & 3) * 32;
    #pragma unroll
    for (int mt = 0; mt < 4; mt++) {
        int r0 = row0 + warp_m + mt*16 + (lane >> 2);
        #pragma unroll
        for (int nt = 0; nt < 4; nt++) {
            int col = col0 + warp_n + nt*8 + (lane & 3) * 2;
            int h = col >> 6, dd = col & 63;
            #pragma unroll
            for (int half = 0; half < 2; half++) {
                int r = r0 + half*8;
                int n = r >> 11, s = r & (SEQ - 1);
                float vx = acc[mt][nt][2*half], vy = acc[mt][nt][2*half+1];
                size_t off = (((size_t)(n*HEADS + h)*SEQ + s))*HD + dd;
                float2 f2 = {vx, vy};
                *(float2*)(g_v + off) = f2;
                *(__nv_bfloat162*)(g_vb + off) = __floats2bfloat162_rn(vx, vy);
            }
        }
    }
}

// ---------------------------------------------------------------------------
// Output projection (x3) + bias. grid (8, 64).
// ---------------------------------------------------------------------------
__global__ void __launch_bounds__(256) proj_out_kernel(
    const float* __restrict__ bo, float* __restrict__ out)
{
    extern __shared__ char smraw[];
    uint32_t sm = smem_to_u32(smraw);
    const __nv_bfloat16* Bh = g_wh + (size_t)3 * DIM * DIM;
    const __nv_bfloat16* Bl = g_wl + (size_t)3 * DIM * DIM;
    const int row0 = blockIdx.y * 128, col0 = blockIdx.x * 128;

    float acc[4][4][4] = {};
    gemm128_pipe<true>(g_ah, g_al, Bh, Bl, row0, col0, sm, acc);

    const int lane = threadIdx.x & 31, wid = threadIdx.x >> 5;
    const int warp_m = (wid >> 2) * 64, warp_n = (wid & 3) * 32;
    #pragma unroll
    for (int mt = 0; mt < 4; mt++) {
        int r0 = row0 + warp_m + mt*16 + (lane >> 2);
        #pragma unroll
        for (int nt = 0; nt < 4; nt++) {
            int col = col0 + warp_n + nt*8 + (lane & 3) * 2;
            float2 bb = *(const float2*)(bo + col);
            #pragma unroll
            for (int half = 0; half < 2; half++) {
                int r = r0 + half*8;
                float2 f2 = {acc[mt][nt][2*half] + bb.x, acc[mt][nt][2*half+1] + bb.y};
                *(float2*)(out + (size_t)r * DIM + col) = f2;
            }
        }
    }
}

// ---------------------------------------------------------------------------
// Exclusive prefix sum of V (two-pass, 8 chunks of 256).
// ---------------------------------------------------------------------------
__global__ void prefix_a_kernel()   // grid (NH, 8), block 64
{
    const int nh = blockIdx.x, sc = blockIdx.y, dd = threadIdx.x;
    const float* v = g_v + ((size_t)nh * SEQ + sc * 256) * HD + dd;
    float s = 0.0f;
    for (int t = 0; t < 256; t++) s += v[(size_t)t * HD];
    g_psum[nh][sc][dd] = s;
}
__global__ void prefix_b_kernel()   // grid (NH, 8), block 64
{
    const int nh = blockIdx.x, sc = blockIdx.y, dd = threadIdx.x;
    float run = 0.0f;
    for (int c = 0; c < sc; c++) run += g_psum[nh][c][dd];
    const float* v  = g_v  + ((size_t)nh * SEQ + sc * 256) * HD + dd;
    float*       pv = g_pv + ((size_t)nh * SEQ + sc * 256) * HD + dd;
    for (int t = 0; t < 256; t++) {
        pv[(size_t)t * HD] = run;
        run += v[(size_t)t * HD];
    }
}

// ---------------------------------------------------------------------------
// Flash attention on mma.sync + post-softmax correction, cp.async pipelined:
//   out = softmax(QK^T/8) @ V - 1e9 * prefixsum(V)
// BM=128 (8 warps x m16), BN=64, double-buffered K/V, 1 sync per tile.
// grid (16, 64), 256 threads. Dynamic smem 55296 B.
// ---------------------------------------------------------------------------
#define AP 72                       // pitch (bf16), 144B rows
#define AQ_BYTES (128*AP*2)         // 18432
#define AKV_BYTES (64*AP*2)         // 9216
#define AKV_STAGE (2*AKV_BYTES)     // K + V per stage
#define ATTN_SMEM (AQ_BYTES + 2*AKV_STAGE)   // 55296

__global__ void __launch_bounds__(256) attn_kernel()
{
    extern __shared__ char smraw[];
    const uint32_t sm = smem_to_u32(smraw);
    const uint32_t qs_b = sm;
    const int tid = threadIdx.x, lane = tid & 31, wid = tid >> 5;
    const int nh = blockIdx.y, q0 = blockIdx.x * 128;
    const __nv_bfloat16* qg = g_qb + (size_t)nh * SEQ * HD;
    const __nv_bfloat16* kg = g_kb + (size_t)nh * SEQ * HD;
    const __nv_bfloat16* vg = g_vb + (size_t)nh * SEQ * HD;

    const int lr = tid >> 3;          // 0..31
    const int lc = (tid & 7) * 8;     // 0..56
    const uint32_t kvo1 = (uint32_t)((lr * AP + lc) * 2);
    const uint32_t kvo2 = (uint32_t)(((lr + 32) * AP + lc) * 2);

    auto issue_kv = [&](int kt, int buf) {
        uint32_t base = sm + AQ_BYTES + buf * AKV_STAGE;
        const __nv_bfloat16* kp = kg + (size_t)(kt*64 + lr) * HD + lc;
        const __nv_bfloat16* vp = vg + (size_t)(kt*64 + lr) * HD + lc;
        CP16(base + kvo1, kp);
        CP16(base + kvo2, kp + 32 * HD);
        CP16(base + AKV_BYTES + kvo1, vp);
        CP16(base + AKV_BYTES + kvo2, vp + 32 * HD);
        CP_COMMIT();
    };

    // prologue: Q (group together with KV0)
    {
        const int qr = tid >> 3, qc = (tid & 7) * 8;
        #pragma unroll
        for (int i = 0; i < 4; i++) {
            int r = qr + i * 32;
            CP16(qs_b + (uint32_t)((r * AP + qc) * 2), qg + (size_t)(q0 + r) * HD + qc);
        }
    }
    issue_kv(0, 0);

    uint32_t qf[4][4];
    const int m0 = wid * 16;
    float o[8][4] = {};
    float mr0 = -1e30f, mr1 = -1e30f, lr0 = 0.0f, lr1 = 0.0f;

    for (int kt = 0; kt < SEQ/64; kt++) {
        CP_WAIT0();
        __syncthreads();
        if (kt + 1 < SEQ/64) issue_kv(kt + 1, (kt + 1) & 1);

        if (kt == 0) {
            #pragma unroll
            for (int ks = 0; ks < 4; ks++) {
                uint32_t ad = qs_b + (uint32_t)(((m0 + (lane&15))*AP + ks*16)*2 + (lane&16));
                LDSM_X4(qf[ks], ad);
            }
        }

        const uint32_t ks_b = sm + AQ_BYTES + (kt & 1) * AKV_STAGE;
        const uint32_t vs_b = ks_b + AKV_BYTES;

        // S = Q K^T : 8 n-tiles (64 keys), k = 64 (4 ksteps)
        float sf[8][4] = {};
        #pragma unroll
        for (int ks = 0; ks < 4; ks++) {
            uint32_t bfr[4][4];
            #pragma unroll
            for (int p = 0; p < 4; p++) {
                uint32_t bd = ks_b + (uint32_t)(((p*16 + (lane&7) + ((lane&16)>>1))*AP + ks*16)*2 + ((lane&8)<<1));
                LDSM_X4(bfr[p], bd);
            }
            #pragma unroll
            for (int p = 0; p < 4; p++) {
                MMA_BF16(sf[2*p],   qf[ks], bfr[p][0], bfr[p][1]);
                MMA_BF16(sf[2*p+1], qf[ks], bfr[p][2], bfr[p][3]);
            }
        }

        // online softmax: thread owns 2 rows (lane/4, +8)
        float mx0 = -1e30f, mx1 = -1e30f;
        #pragma unroll
        for (int nt = 0; nt < 8; nt++) {
            mx0 = fmaxf(mx0, fmaxf(sf[nt][0], sf[nt][1]));
            mx1 = fmaxf(mx1, fmaxf(sf[nt][2], sf[nt][3]));
        }
        mx0 = fmaxf(mx0, __shfl_xor_sync(0xffffffffu, mx0, 1));
        mx0 = fmaxf(mx0, __shfl_xor_sync(0xffffffffu, mx0, 2));
        mx1 = fmaxf(mx1, __shfl_xor_sync(0xffffffffu, mx1, 1));
        mx1 = fmaxf(mx1, __shfl_xor_sync(0xffffffffu, mx1, 2));
        float mn0 = fmaxf(mr0, mx0), mn1 = fmaxf(mr1, mx1);
        float c0 = __expf(mr0 - mn0), c1 = __expf(mr1 - mn1);
        mr0 = mn0; mr1 = mn1;

        uint32_t pf[4][4];
        float s0 = 0.0f, s1 = 0.0f;
        #pragma unroll
        for (int g = 0; g < 4; g++) {
            float e00 = __expf(sf[2*g][0]   - mn0), e01 = __expf(sf[2*g][1]   - mn0);
            float e02 = __expf(sf[2*g][2]   - mn1), e03 = __expf(sf[2*g][3]   - mn1);
            float e10 = __expf(sf[2*g+1][0] - mn0), e11 = __expf(sf[2*g+1][1] - mn0);
            float e12 = __expf(sf[2*g+1][2] - mn1), e13 = __expf(sf[2*g+1][3] - mn1);
            s0 += (e00 + e01) + (e10 + e11);
            s1 += (e02 + e03) + (e12 + e13);
            pf[g][0] = packbf2(e00, e01);
            pf[g][1] = packbf2(e02, e03);
            pf[g][2] = packbf2(e10, e11);
            pf[g][3] = packbf2(e12, e13);
        }
        s0 += __shfl_xor_sync(0xffffffffu, s0, 1);
        s0 += __shfl_xor_sync(0xffffffffu, s0, 2);
        s1 += __shfl_xor_sync(0xffffffffu, s1, 1);
        s1 += __shfl_xor_sync(0xffffffffu, s1, 2);
        lr0 = lr0 * c0 + s0;
        lr1 = lr1 * c1 + s1;
        #pragma unroll
        for (int nt = 0; nt < 8; nt++) {
            o[nt][0] *= c0; o[nt][1] *= c0;
            o[nt][2] *= c1; o[nt][3] *= c1;
        }

        // O += P @ V : V via ldmatrix.trans
        #pragma unroll
        for (int g = 0; g < 4; g++) {
            uint32_t vf[4][4];
            #pragma unroll
            for (int p = 0; p < 4; p++) {
                uint32_t vd = vs_b + (uint32_t)(((g*16 + (lane&7) + (lane&8))*AP + p*16)*2 + (lane&16));
                LDSM_X4_T(vf[p], vd);
            }
            #pragma unroll
            for (int p = 0; p < 4; p++) {
                MMA_BF16(o[2*p],   pf[g], vf[p][0], vf[p][1]);
                MMA_BF16(o[2*p+1], pf[g], vf[p][2], vf[p][3]);
            }
        }
        __syncthreads();   // retire stage before overwrite
    }

    // epilogue: r = o/l - 1e9*pv; bf16 hi/lo split -> g_ah/g_al [n*s][h*64+dd]
    const int n = nh >> 4, hh = nh & 15;
    const int srow0 = q0 + m0 + (lane >> 2);
    const float i0 = 1.0f / lr0, i1 = 1.0f / lr1;
    #pragma unroll
    for (int nt = 0; nt < 8; nt++) {
        int dd = nt*8 + (lane & 3) * 2;
        #pragma unroll
        for (int half = 0; half < 2; half++) {
            int s = srow0 + half*8;
            float inv = half ? i1 : i0;
            float2 pv = *(const float2*)(g_pv + ((size_t)nh * SEQ + s) * HD + dd);
            float rx = o[nt][2*half]   * inv - NEGC * pv.x;
            float ry = o[nt][2*half+1] * inv - NEGC * pv.y;
            __nv_bfloat16 hx = __float2bfloat16(rx);
            __nv_bfloat16 hy = __float2bfloat16(ry);
            __nv_bfloat16 lx = __float2bfloat16(rx - __bfloat162float(hx));
            __nv_bfloat16 ly = __float2bfloat16(ry - __bfloat162float(hy));
            size_t off = ((size_t)(n * SEQ + s)) * DIM + hh * HD + dd;
            __nv_bfloat162 hv; hv.x = hx; hv.y = hy;
            __nv_bfloat162 lv; lv.x = lx; lv.y = ly;
            *(__nv_bfloat162*)(g_ah + off) = hv;
            *(__nv_bfloat162*)(g_al + off) = lv;
        }
    }
}

// ---------------------------------------------------------------------------
extern "C" void kernel_launch(void* const* d_in, const int* in_sizes, int n_in,
                              void* d_out, int out_size)
{
    const float* x  = (const float*)d_in[0];
    const float* wq = (const float*)d_in[1];
    const float* wk = (const float*)d_in[2];
    const float* wv = (const float*)d_in[3];
    const float* wo = (const float*)d_in[4];
    const float* bo = (const float*)d_in[5];
    float* out = (float*)d_out;

    const int SM_X1 = 2 * 2 * TILEB;          // 40960
    const int SM_X3 = 2 * 4 * TILEB;          // 81920

    cudaFuncSetAttribute(proj_qk_kernel,
                         cudaFuncAttributeMaxDynamicSharedMemorySize, SM_X1);
    cudaFuncSetAttribute(proj_v_kernel,
                         cudaFuncAttributeMaxDynamicSharedMemorySize, SM_X3);
    cudaFuncSetAttribute(proj_out_kernel,
                         cudaFuncAttributeMaxDynamicSharedMemorySize, SM_X3);
    cudaFuncSetAttribute(attn_kernel,
                         cudaFuncAttributeMaxDynamicSharedMemorySize, ATTN_SMEM);

    split_x_kernel<<<NS*DIM/(256*4), 256>>>(x);
    split_w_kernel<<<dim3(DIM*DIM/(256*4), 4), 256>>>(wq, wk, wv, wo);
    proj_qk_kernel<<<dim3(DIM/128, NS/128, 2), 256, SM_X1>>>();
    proj_v_kernel<<<dim3(DIM/128, NS/128), 256, SM_X3>>>();
    prefix_a_kernel<<<dim3(NH, 8), HD>>>();
    prefix_b_kernel<<<dim3(NH, 8), HD>>>();
    attn_kernel<<<dim3(SEQ/128, NH), 256, ATTN_SMEM>>>();
    proj_out_kernel<<<dim3(DIM/128, NS/128), 256, SM_X3>>>(bo, out);
}